// round 1
// baseline (speedup 1.0000x reference)
#include <cuda_runtime.h>

#define TT 1024
#define DM 512
#define NB 4
#define NH 8
#define DK 64
#define LL 2047   // 2*T - 1

// ---------------- scratch (device globals; no allocations allowed) ----------------
__device__ float g_Q[NB * TT * DM];
__device__ float g_K[NB * TT * DM];
__device__ float g_V[NB * TT * DM];
__device__ float g_P[2048 * DM];
__device__ float g_R[32LL * 512 * LL];   // [b*8+h][m][l]
__device__ float g_S[32LL * TT * TT];    // [b*8+h][t][s]
__device__ float g_O[NB * TT * DM];

// ---------------- generic NN GEMM: C[M,N] = A[M,K] @ B[K,N] (+bias[n]) ----------------
// 64x64 block tile, BK=16, 256 threads, 4x4 register micro-tile.
// Batched over blockIdx.z via (b,h) strides. N must be a multiple of 64 relative
// to in-bounds reads (true for all uses). M may be ragged (guarded).
__global__ void __launch_bounds__(256) gemm_nn(
    const float* __restrict__ A, int lda, long long sAb, long long sAh,
    const float* __restrict__ B, int ldb, long long sBb, long long sBh,
    float* __restrict__ C, int ldc, long long sCb, long long sCh,
    int M, int N, int K, const float* __restrict__ bias)
{
    int z = blockIdx.z, b = z >> 3, h = z & 7;
    A += (long long)b * sAb + (long long)h * sAh;
    B += (long long)b * sBb + (long long)h * sBh;
    C += (long long)b * sCb + (long long)h * sCh;

    __shared__ float As[16][64];
    __shared__ float Bs[16][64];

    const int tid = threadIdx.x;
    const int tx = tid & 15, ty = tid >> 4;
    const int m0 = blockIdx.y * 64, n0 = blockIdx.x * 64;
    const int lm = tid >> 2, lk = (tid & 3) << 2;      // A load: row lm, 4 k's
    const int lkb = tid >> 4, lnb = (tid & 15) << 2;   // B load: k-row lkb, 4 n's

    float acc[4][4] = {};

    for (int k0 = 0; k0 < K; k0 += 16) {
        float4 a = make_float4(0.f, 0.f, 0.f, 0.f);
        if (m0 + lm < M)
            a = *(const float4*)(A + (long long)(m0 + lm) * lda + k0 + lk);
        As[lk + 0][lm] = a.x; As[lk + 1][lm] = a.y;
        As[lk + 2][lm] = a.z; As[lk + 3][lm] = a.w;

        *(float4*)&Bs[lkb][lnb] =
            *(const float4*)(B + (long long)(k0 + lkb) * ldb + n0 + lnb);
        __syncthreads();

#pragma unroll
        for (int kk = 0; kk < 16; kk++) {
            float4 av = *(float4*)&As[kk][ty << 2];
            float4 bv = *(float4*)&Bs[kk][tx << 2];
            float aa[4] = {av.x, av.y, av.z, av.w};
            float bb[4] = {bv.x, bv.y, bv.z, bv.w};
#pragma unroll
            for (int i = 0; i < 4; i++)
#pragma unroll
                for (int j = 0; j < 4; j++)
                    acc[i][j] = fmaf(aa[i], bb[j], acc[i][j]);
        }
        __syncthreads();
    }

#pragma unroll
    for (int i = 0; i < 4; i++) {
        int m = m0 + (ty << 2) + i;
        if (m < M) {
#pragma unroll
            for (int j = 0; j < 4; j++) {
                int n = n0 + (tx << 2) + j;
                float v = acc[i][j];
                if (bias) v += bias[n];
                C[(long long)m * ldc + n] = v;
            }
        }
    }
}

// ---------------- R = (Q[:,512:1024,h,:] + pos_bias_v) @ P_h^T ----------------
// per z=(b,h): A[512,64] (lda=DM), B[2047,64] (ldb=DM), C[512,2047]
__global__ void __launch_bounds__(256) gemm_tn_R(
    const float* __restrict__ Q, const float* __restrict__ P,
    const float* __restrict__ pbv, float* __restrict__ Rr)
{
    int z = blockIdx.z, b = z >> 3, h = z & 7;
    const float* A  = Q + ((long long)b * TT + 512) * DM + h * DK;
    const float* Bp = P + h * DK;
    float* C = Rr + (long long)z * 512 * LL;

    __shared__ float As[16][64];
    __shared__ float Bs[16][64];

    const int tid = threadIdx.x;
    const int tx = tid & 15, ty = tid >> 4;
    const int m0 = blockIdx.y * 64, n0 = blockIdx.x * 64;
    const int lr = tid >> 2, lk = (tid & 3) << 2;

    float acc[4][4] = {};

    for (int k0 = 0; k0 < DK; k0 += 16) {
        float4 bias4 = *(const float4*)(pbv + h * DK + k0 + lk);
        float4 a = *(const float4*)(A + (long long)(m0 + lr) * DM + k0 + lk);
        As[lk + 0][lr] = a.x + bias4.x; As[lk + 1][lr] = a.y + bias4.y;
        As[lk + 2][lr] = a.z + bias4.z; As[lk + 3][lr] = a.w + bias4.w;

        float4 bb = make_float4(0.f, 0.f, 0.f, 0.f);
        if (n0 + lr < LL)
            bb = *(const float4*)(Bp + (long long)(n0 + lr) * DM + k0 + lk);
        Bs[lk + 0][lr] = bb.x; Bs[lk + 1][lr] = bb.y;
        Bs[lk + 2][lr] = bb.z; Bs[lk + 3][lr] = bb.w;
        __syncthreads();

#pragma unroll
        for (int kk = 0; kk < 16; kk++) {
            float4 av = *(float4*)&As[kk][ty << 2];
            float4 bv = *(float4*)&Bs[kk][tx << 2];
            float aa[4] = {av.x, av.y, av.z, av.w};
            float bb2[4] = {bv.x, bv.y, bv.z, bv.w};
#pragma unroll
            for (int i = 0; i < 4; i++)
#pragma unroll
                for (int j = 0; j < 4; j++)
                    acc[i][j] = fmaf(aa[i], bb2[j], acc[i][j]);
        }
        __syncthreads();
    }

#pragma unroll
    for (int i = 0; i < 4; i++) {
        int m = m0 + (ty << 2) + i;
#pragma unroll
        for (int j = 0; j < 4; j++) {
            int n = n0 + (tx << 2) + j;
            if (n < LL) C[(long long)m * LL + n] = acc[i][j];
        }
    }
}

// ---------------- S = ((Q + pos_bias_u) @ K^T + relshift(R)) * 0.125, masked ----------------
// per z=(b,h): A[1024,64], B[1024,64], C[1024,1024]
__global__ void __launch_bounds__(256) gemm_tn_S(
    const float* __restrict__ Q, const float* __restrict__ Kt,
    const float* __restrict__ pbu, const float* __restrict__ Rr,
    const unsigned char* __restrict__ mask, float* __restrict__ S)
{
    int z = blockIdx.z, b = z >> 3, h = z & 7;
    const float* A  = Q  + (long long)b * TT * DM + h * DK;
    const float* Bk = Kt + (long long)b * TT * DM + h * DK;

    __shared__ float As[16][64];
    __shared__ float Bs[16][64];

    const int tid = threadIdx.x;
    const int tx = tid & 15, ty = tid >> 4;
    const int m0 = blockIdx.y * 64, n0 = blockIdx.x * 64;
    const int lr = tid >> 2, lk = (tid & 3) << 2;

    float acc[4][4] = {};

    for (int k0 = 0; k0 < DK; k0 += 16) {
        float4 bias4 = *(const float4*)(pbu + h * DK + k0 + lk);
        float4 a = *(const float4*)(A + (long long)(m0 + lr) * DM + k0 + lk);
        As[lk + 0][lr] = a.x + bias4.x; As[lk + 1][lr] = a.y + bias4.y;
        As[lk + 2][lr] = a.z + bias4.z; As[lk + 3][lr] = a.w + bias4.w;

        float4 bb = *(const float4*)(Bk + (long long)(n0 + lr) * DM + k0 + lk);
        Bs[lk + 0][lr] = bb.x; Bs[lk + 1][lr] = bb.y;
        Bs[lk + 2][lr] = bb.z; Bs[lk + 3][lr] = bb.w;
        __syncthreads();

#pragma unroll
        for (int kk = 0; kk < 16; kk++) {
            float4 av = *(float4*)&As[kk][ty << 2];
            float4 bv = *(float4*)&Bs[kk][tx << 2];
            float aa[4] = {av.x, av.y, av.z, av.w};
            float bb2[4] = {bv.x, bv.y, bv.z, bv.w};
#pragma unroll
            for (int i = 0; i < 4; i++)
#pragma unroll
                for (int j = 0; j < 4; j++)
                    acc[i][j] = fmaf(aa[i], bb2[j], acc[i][j]);
        }
        __syncthreads();
    }

    const long long zb = (long long)z * TT * TT;
    const long long rb = (long long)z * 512 * LL;
    const long long mb = (long long)b * TT * TT;
#pragma unroll
    for (int i = 0; i < 4; i++) {
        int t = m0 + (ty << 2) + i;
#pragma unroll
        for (int j = 0; j < 4; j++) {
            int s = n0 + (tx << 2) + j;
            int l = s + ((t & 1) << 10);
            float pos = (l == LL) ? 0.f : Rr[rb + (long long)(t >> 1) * LL + l];
            float val = (acc[i][j] + pos) * 0.125f;
            if (mask[mb + (long long)t * TT + s]) val = -1e9f;
            S[zb + (long long)t * TT + s] = val;
        }
    }
}

// ---------------- row softmax over last dim (1024), one block per row ----------------
__global__ void __launch_bounds__(256) softmax_k(float* __restrict__ S)
{
    __shared__ float red1[8];
    __shared__ float red2[8];
    long long row = blockIdx.x;
    float* p = S + row * (long long)TT;
    int tid = threadIdx.x;

    float4 v = *(float4*)(p + (tid << 2));
    float mx = fmaxf(fmaxf(v.x, v.y), fmaxf(v.z, v.w));
#pragma unroll
    for (int o = 16; o; o >>= 1) mx = fmaxf(mx, __shfl_xor_sync(0xffffffffu, mx, o));
    if ((tid & 31) == 0) red1[tid >> 5] = mx;
    __syncthreads();
    mx = red1[0];
#pragma unroll
    for (int i = 1; i < 8; i++) mx = fmaxf(mx, red1[i]);

    v.x = __expf(v.x - mx); v.y = __expf(v.y - mx);
    v.z = __expf(v.z - mx); v.w = __expf(v.w - mx);
    float sum = v.x + v.y + v.z + v.w;
#pragma unroll
    for (int o = 16; o; o >>= 1) sum += __shfl_xor_sync(0xffffffffu, sum, o);
    if ((tid & 31) == 0) red2[tid >> 5] = sum;
    __syncthreads();
    sum = red2[0];
#pragma unroll
    for (int i = 1; i < 8; i++) sum += red2[i];

    float inv = 1.f / sum;
    v.x *= inv; v.y *= inv; v.z *= inv; v.w *= inv;
    *(float4*)(p + (tid << 2)) = v;
}

// ---------------- launch ----------------
extern "C" void kernel_launch(void* const* d_in, const int* in_sizes, int n_in,
                              void* d_out, int out_size)
{
    const float* x   = (const float*)d_in[0];
    const float* pos = (const float*)d_in[1];
    const unsigned char* mask = (const unsigned char*)d_in[2];
    const float* Wq = (const float*)d_in[3];  const float* bq = (const float*)d_in[4];
    const float* Wk = (const float*)d_in[5];  const float* bk = (const float*)d_in[6];
    const float* Wv = (const float*)d_in[7];  const float* bv = (const float*)d_in[8];
    const float* Wp = (const float*)d_in[9];  const float* bp = (const float*)d_in[10];
    const float* Wo = (const float*)d_in[11]; const float* bo = (const float*)d_in[12];
    const float* pbu = (const float*)d_in[13];
    const float* pbv = (const float*)d_in[14];
    float* out = (float*)d_out;

    float *Q, *K, *V, *P, *R, *S, *O;
    cudaGetSymbolAddress((void**)&Q, g_Q);
    cudaGetSymbolAddress((void**)&K, g_K);
    cudaGetSymbolAddress((void**)&V, g_V);
    cudaGetSymbolAddress((void**)&P, g_P);
    cudaGetSymbolAddress((void**)&R, g_R);
    cudaGetSymbolAddress((void**)&S, g_S);
    cudaGetSymbolAddress((void**)&O, g_O);

    dim3 blk(256);

    // projections: Q/K/V = x@W + b ; P = pos_emb@Wp + bp
    gemm_nn<<<dim3(8, 64, 1), blk>>>(x, DM, 0, 0, Wq, DM, 0, 0, Q, DM, 0, 0,
                                     NB * TT, DM, DM, bq);
    gemm_nn<<<dim3(8, 64, 1), blk>>>(x, DM, 0, 0, Wk, DM, 0, 0, K, DM, 0, 0,
                                     NB * TT, DM, DM, bk);
    gemm_nn<<<dim3(8, 64, 1), blk>>>(x, DM, 0, 0, Wv, DM, 0, 0, V, DM, 0, 0,
                                     NB * TT, DM, DM, bv);
    gemm_nn<<<dim3(8, 32, 1), blk>>>(pos, DM, 0, 0, Wp, DM, 0, 0, P, DM, 0, 0,
                                     LL, DM, DM, bp);

    // R = (Q[512:] + pos_bias_v) @ P^T   per (b,h)
    gemm_tn_R<<<dim3(32, 8, 32), blk>>>(Q, P, pbv, R);

    // S = ((Q + pos_bias_u) @ K^T + relshift(R)) / 8, masked
    gemm_tn_S<<<dim3(16, 16, 32), blk>>>(Q, K, pbu, R, mask, S);

    // softmax rows
    softmax_k<<<32 * TT, 256>>>(S);

    // O = attn @ V   per (b,h)
    gemm_nn<<<dim3(1, 16, 32), blk>>>(S, TT, 8LL * TT * TT, (long long)TT * TT,
                                      V, DM, (long long)TT * DM, 64,
                                      O, DM, (long long)TT * DM, 64,
                                      TT, DK, TT, nullptr);

    // out = O @ Wo + bo
    gemm_nn<<<dim3(8, 64, 1), blk>>>(O, DM, 0, 0, Wo, DM, 0, 0, out, DM, 0, 0,
                                     NB * TT, DM, DM, bo);
}

// round 2
// speedup vs baseline: 1.2814x; 1.2814x over previous
#include <cuda_runtime.h>
#include <cstdint>

#define TT 1024
#define DM 512
#define NB 4
#define NH 8
#define DK 64
#define LL 2047   // 2*T - 1

// ---------------- scratch (device globals; no allocations allowed) ----------------
__device__ float g_Q[NB * TT * DM];
__device__ float g_K[NB * TT * DM];
__device__ float g_V[NB * TT * DM];
__device__ float g_P[2048 * DM];
__device__ float g_R[32LL * 512 * LL];   // [b*8+h][m][l]
__device__ float g_S[32LL * TT * TT];    // [b*8+h][t][s]
__device__ float g_O[NB * TT * DM];

// ---------------- tf32 split helpers ----------------
__device__ __forceinline__ void split_tf32(float x, float& hi, float& lo) {
    uint32_t uh;
    asm("cvt.rna.tf32.f32 %0, %1;" : "=r"(uh) : "f"(x));
    hi = __uint_as_float(uh);
    float r = x - hi;
    uint32_t ul;
    asm("cvt.rna.tf32.f32 %0, %1;" : "=r"(ul) : "f"(r));
    lo = __uint_as_float(ul);
}

__device__ __forceinline__ void mma_tf32(float* d, const uint32_t* a, const uint32_t* b) {
    asm volatile(
        "mma.sync.aligned.m16n8k8.row.col.f32.tf32.tf32.f32 "
        "{%0,%1,%2,%3}, {%4,%5,%6,%7}, {%8,%9}, {%0,%1,%2,%3};\n"
        : "+f"(d[0]), "+f"(d[1]), "+f"(d[2]), "+f"(d[3])
        : "r"(a[0]), "r"(a[1]), "r"(a[2]), "r"(a[3]), "r"(b[0]), "r"(b[1]));
}

// ---------------- unified tf32x3 tensor-core GEMM ----------------
// C[M,N] = A[M,K] @ op(B) (+epilogue), 128x64 block tile, BK=32, 256 threads.
// TRANSB=0: B global is [K,N] row-major. TRANSB=1: B global is [N,K] row-major (C=A@B^T).
// aBias: optional per-head K-vector added to A rows (pos_bias_u/v), indexed by h=z&7.
// EPI=0: C = acc (+ bias[n]).  EPI=2: rel-shift + mask + scale epilogue into S.
// smem: AsH/AsL [128][36], BsH/BsL [32][72]  (55296 bytes dynamic)
#define ASTR 36
#define BSTR 72
#define GEMM_SMEM ((2 * 128 * ASTR + 2 * 32 * BSTR) * 4)

template <int TRANSB, int EPI>
__global__ void __launch_bounds__(256) mma_gemm(
    const float* __restrict__ A, int lda, long long sAb, long long sAh,
    const float* __restrict__ B, int ldb, long long sBb, long long sBh,
    float* __restrict__ C, int ldc, long long sCb, long long sCh,
    int M, int N, int K,
    const float* __restrict__ bias,
    const float* __restrict__ aBias,
    const float* __restrict__ Rr,
    const unsigned char* __restrict__ mask)
{
    extern __shared__ float sm[];
    float* AsH = sm;
    float* AsL = AsH + 128 * ASTR;
    float* BsH = AsL + 128 * ASTR;
    float* BsL = BsH + 32 * BSTR;

    const int z = blockIdx.z, b = z >> 3, h = z & 7;
    A += (long long)b * sAb + (long long)h * sAh;
    B += (long long)b * sBb + (long long)h * sBh;
    const float* ab = aBias ? (aBias + h * DK) : nullptr;

    const int tid = threadIdx.x;
    const int lane = tid & 31, wid = tid >> 5;
    const int g = lane >> 2, t = lane & 3;
    const int wm = wid & 3, wn = wid >> 2;
    const int m0 = blockIdx.y * 128, n0 = blockIdx.x * 64;

    // loader indices
    const int a_m = tid >> 3;            // 0..31
    const int a_k4 = (tid & 7) << 2;     // 0..28 step 4
    const int bn_nq = (tid & 15) << 2;   // NN: n offset
    const int bn_k = tid >> 4;           // NN: k row
    const int bt_n = tid & 63;           // TN: n row
    const int bt_k4 = (tid >> 6) << 2;   // TN: k offset

    float d[2][4][4];
#pragma unroll
    for (int i = 0; i < 2; i++)
#pragma unroll
        for (int j = 0; j < 4; j++)
#pragma unroll
            for (int c = 0; c < 4; c++) d[i][j][c] = 0.f;

    for (int k0 = 0; k0 < K; k0 += 32) {
        // ---- A tile -> smem (with tf32 split, optional row-bias) ----
        float4 abv = make_float4(0.f, 0.f, 0.f, 0.f);
        if (ab) abv = *(const float4*)(ab + k0 + a_k4);
#pragma unroll
        for (int r = 0; r < 4; r++) {
            int m = a_m + 32 * r;
            float4 v = make_float4(0.f, 0.f, 0.f, 0.f);
            if (m0 + m < M)
                v = *(const float4*)(A + (long long)(m0 + m) * lda + k0 + a_k4);
            v.x += abv.x; v.y += abv.y; v.z += abv.z; v.w += abv.w;
            float4 hv, lv;
            split_tf32(v.x, hv.x, lv.x); split_tf32(v.y, hv.y, lv.y);
            split_tf32(v.z, hv.z, lv.z); split_tf32(v.w, hv.w, lv.w);
            *(float4*)(AsH + m * ASTR + a_k4) = hv;
            *(float4*)(AsL + m * ASTR + a_k4) = lv;
        }
        // ---- B tile -> smem (Bs[k][n]) ----
        if (!TRANSB) {
#pragma unroll
            for (int r = 0; r < 2; r++) {
                int k = bn_k + 16 * r;
                float4 v = *(const float4*)(B + (long long)(k0 + k) * ldb + n0 + bn_nq);
                float4 hv, lv;
                split_tf32(v.x, hv.x, lv.x); split_tf32(v.y, hv.y, lv.y);
                split_tf32(v.z, hv.z, lv.z); split_tf32(v.w, hv.w, lv.w);
                *(float4*)(BsH + k * BSTR + bn_nq) = hv;
                *(float4*)(BsL + k * BSTR + bn_nq) = lv;
            }
        } else {
#pragma unroll
            for (int r = 0; r < 2; r++) {
                int kq = bt_k4 + 16 * r;
                float4 v = make_float4(0.f, 0.f, 0.f, 0.f);
                if (n0 + bt_n < N)
                    v = *(const float4*)(B + (long long)(n0 + bt_n) * ldb + k0 + kq);
                float hh, ll;
                split_tf32(v.x, hh, ll); BsH[(kq + 0) * BSTR + bt_n] = hh; BsL[(kq + 0) * BSTR + bt_n] = ll;
                split_tf32(v.y, hh, ll); BsH[(kq + 1) * BSTR + bt_n] = hh; BsL[(kq + 1) * BSTR + bt_n] = ll;
                split_tf32(v.z, hh, ll); BsH[(kq + 2) * BSTR + bt_n] = hh; BsL[(kq + 2) * BSTR + bt_n] = ll;
                split_tf32(v.w, hh, ll); BsH[(kq + 3) * BSTR + bt_n] = hh; BsL[(kq + 3) * BSTR + bt_n] = ll;
            }
        }
        __syncthreads();

        // ---- compute: 4 k-steps of m16n8k8, 3 MMAs per tile (hi*hi, hi*lo, lo*hi) ----
#pragma unroll
        for (int ks = 0; ks < 4; ks++) {
            const int kb = ks * 8;
            uint32_t aH[2][4], aL[2][4], bH[4][2], bL[4][2];
#pragma unroll
            for (int mt = 0; mt < 2; mt++) {
                int r0 = (wm * 32 + mt * 16 + g) * ASTR;
                int r1 = r0 + 8 * ASTR;
                aH[mt][0] = __float_as_uint(AsH[r0 + kb + t]);
                aH[mt][1] = __float_as_uint(AsH[r1 + kb + t]);
                aH[mt][2] = __float_as_uint(AsH[r0 + kb + t + 4]);
                aH[mt][3] = __float_as_uint(AsH[r1 + kb + t + 4]);
                aL[mt][0] = __float_as_uint(AsL[r0 + kb + t]);
                aL[mt][1] = __float_as_uint(AsL[r1 + kb + t]);
                aL[mt][2] = __float_as_uint(AsL[r0 + kb + t + 4]);
                aL[mt][3] = __float_as_uint(AsL[r1 + kb + t + 4]);
            }
#pragma unroll
            for (int nt = 0; nt < 4; nt++) {
                int c = wn * 32 + nt * 8 + g;
                bH[nt][0] = __float_as_uint(BsH[(kb + t) * BSTR + c]);
                bH[nt][1] = __float_as_uint(BsH[(kb + t + 4) * BSTR + c]);
                bL[nt][0] = __float_as_uint(BsL[(kb + t) * BSTR + c]);
                bL[nt][1] = __float_as_uint(BsL[(kb + t + 4) * BSTR + c]);
            }
#pragma unroll
            for (int mt = 0; mt < 2; mt++)
#pragma unroll
                for (int nt = 0; nt < 4; nt++) {
                    mma_tf32(d[mt][nt], aH[mt], bH[nt]);
                    mma_tf32(d[mt][nt], aH[mt], bL[nt]);
                    mma_tf32(d[mt][nt], aL[mt], bH[nt]);
                }
        }
        __syncthreads();
    }

    // ---- epilogue ----
    float* Cz = C + (long long)b * sCb + (long long)h * sCh;
#pragma unroll
    for (int mt = 0; mt < 2; mt++) {
        int row = m0 + wm * 32 + mt * 16 + g;
#pragma unroll
        for (int nt = 0; nt < 4; nt++) {
            int col = n0 + wn * 32 + nt * 8 + 2 * t;
            if (EPI == 0) {
                float b0 = bias ? bias[col] : 0.f;
                float b1 = bias ? bias[col + (col + 1 < N ? 1 : 0)] : 0.f;
                if (row < M) {
                    if (col < N)     Cz[(long long)row * ldc + col]     = d[mt][nt][0] + b0;
                    if (col + 1 < N) Cz[(long long)row * ldc + col + 1] = d[mt][nt][1] + b1;
                }
                if (row + 8 < M) {
                    if (col < N)     Cz[(long long)(row + 8) * ldc + col]     = d[mt][nt][2] + b0;
                    if (col + 1 < N) Cz[(long long)(row + 8) * ldc + col + 1] = d[mt][nt][3] + b1;
                }
            } else {
                // EPI==2: S epilogue (dims exact 1024x1024)
                const long long rb = (long long)z * 512 * LL;
                const long long mb = (long long)b * TT * TT;
#pragma unroll
                for (int ci = 0; ci < 4; ci++) {
                    int tt = row + ((ci >> 1) << 3);
                    int ss = col + (ci & 1);
                    int l = ss + ((tt & 1) << 10);
                    float pos = (l == LL) ? 0.f : Rr[rb + (long long)(tt >> 1) * LL + l];
                    float v = (d[mt][nt][ci] + pos) * 0.125f;
                    if (mask[mb + (long long)tt * TT + ss]) v = -1e9f;
                    Cz[(long long)tt * ldc + ss] = v;
                }
            }
        }
    }
}

// ---------------- row softmax over last dim (1024), one block per row ----------------
__global__ void __launch_bounds__(256) softmax_k(float* __restrict__ S)
{
    __shared__ float red1[8];
    __shared__ float red2[8];
    long long row = blockIdx.x;
    float* p = S + row * (long long)TT;
    int tid = threadIdx.x;

    float4 v = *(float4*)(p + (tid << 2));
    float mx = fmaxf(fmaxf(v.x, v.y), fmaxf(v.z, v.w));
#pragma unroll
    for (int o = 16; o; o >>= 1) mx = fmaxf(mx, __shfl_xor_sync(0xffffffffu, mx, o));
    if ((tid & 31) == 0) red1[tid >> 5] = mx;
    __syncthreads();
    mx = red1[0];
#pragma unroll
    for (int i = 1; i < 8; i++) mx = fmaxf(mx, red1[i]);

    v.x = __expf(v.x - mx); v.y = __expf(v.y - mx);
    v.z = __expf(v.z - mx); v.w = __expf(v.w - mx);
    float sum = v.x + v.y + v.z + v.w;
#pragma unroll
    for (int o = 16; o; o >>= 1) sum += __shfl_xor_sync(0xffffffffu, sum, o);
    if ((tid & 31) == 0) red2[tid >> 5] = sum;
    __syncthreads();
    sum = red2[0];
#pragma unroll
    for (int i = 1; i < 8; i++) sum += red2[i];

    float inv = 1.f / sum;
    v.x *= inv; v.y *= inv; v.z *= inv; v.w *= inv;
    *(float4*)(p + (tid << 2)) = v;
}

// ---------------- launch ----------------
extern "C" void kernel_launch(void* const* d_in, const int* in_sizes, int n_in,
                              void* d_out, int out_size)
{
    const float* x   = (const float*)d_in[0];
    const float* pos = (const float*)d_in[1];
    const unsigned char* mask = (const unsigned char*)d_in[2];
    const float* Wq = (const float*)d_in[3];  const float* bq = (const float*)d_in[4];
    const float* Wk = (const float*)d_in[5];  const float* bk = (const float*)d_in[6];
    const float* Wv = (const float*)d_in[7];  const float* bv = (const float*)d_in[8];
    const float* Wp = (const float*)d_in[9];  const float* bp = (const float*)d_in[10];
    const float* Wo = (const float*)d_in[11]; const float* bo = (const float*)d_in[12];
    const float* pbu = (const float*)d_in[13];
    const float* pbv = (const float*)d_in[14];
    float* out = (float*)d_out;

    float *Q, *K, *V, *P, *R, *S, *O;
    cudaGetSymbolAddress((void**)&Q, g_Q);
    cudaGetSymbolAddress((void**)&K, g_K);
    cudaGetSymbolAddress((void**)&V, g_V);
    cudaGetSymbolAddress((void**)&P, g_P);
    cudaGetSymbolAddress((void**)&R, g_R);
    cudaGetSymbolAddress((void**)&S, g_S);
    cudaGetSymbolAddress((void**)&O, g_O);

    cudaFuncSetAttribute(mma_gemm<0, 0>, cudaFuncAttributeMaxDynamicSharedMemorySize, GEMM_SMEM);
    cudaFuncSetAttribute(mma_gemm<1, 0>, cudaFuncAttributeMaxDynamicSharedMemorySize, GEMM_SMEM);
    cudaFuncSetAttribute(mma_gemm<1, 2>, cudaFuncAttributeMaxDynamicSharedMemorySize, GEMM_SMEM);

    dim3 blk(256);

    // projections: Q/K/V = x@W + b ; P = pos_emb@Wp + bp
    mma_gemm<0, 0><<<dim3(8, 32, 1), blk, GEMM_SMEM>>>(
        x, DM, 0, 0, Wq, DM, 0, 0, Q, DM, 0, 0, NB * TT, DM, DM, bq, nullptr, nullptr, nullptr);
    mma_gemm<0, 0><<<dim3(8, 32, 1), blk, GEMM_SMEM>>>(
        x, DM, 0, 0, Wk, DM, 0, 0, K, DM, 0, 0, NB * TT, DM, DM, bk, nullptr, nullptr, nullptr);
    mma_gemm<0, 0><<<dim3(8, 32, 1), blk, GEMM_SMEM>>>(
        x, DM, 0, 0, Wv, DM, 0, 0, V, DM, 0, 0, NB * TT, DM, DM, bv, nullptr, nullptr, nullptr);
    mma_gemm<0, 0><<<dim3(8, 16, 1), blk, GEMM_SMEM>>>(
        pos, DM, 0, 0, Wp, DM, 0, 0, P, DM, 0, 0, LL, DM, DM, bp, nullptr, nullptr, nullptr);

    // R = (Q[512:] + pos_bias_v) @ P^T   per (b,h): M=512, N=2047, K=64
    mma_gemm<1, 0><<<dim3(32, 4, 32), blk, GEMM_SMEM>>>(
        Q + 512 * DM, DM, (long long)TT * DM, DK,
        P, DM, 0, DK,
        R, LL, 8LL * 512 * LL, (long long)512 * LL,
        512, LL, DK, nullptr, pbv, nullptr, nullptr);

    // S = ((Q + pos_bias_u) @ K^T + relshift(R)) / 8, masked: M=N=1024, K=64
    mma_gemm<1, 2><<<dim3(16, 8, 32), blk, GEMM_SMEM>>>(
        Q, DM, (long long)TT * DM, DK,
        K, DM, (long long)TT * DM, DK,
        S, TT, 8LL * TT * TT, (long long)TT * TT,
        TT, TT, DK, nullptr, pbu, R, mask);

    // softmax rows
    softmax_k<<<32 * TT, 256>>>(S);

    // O = attn @ V   per (b,h): M=1024, N=64, K=1024
    mma_gemm<0, 0><<<dim3(1, 8, 32), blk, GEMM_SMEM>>>(
        S, TT, 8LL * TT * TT, (long long)TT * TT,
        V, DM, (long long)TT * DM, DK,
        O, DM, (long long)TT * DM, DK,
        TT, DK, TT, nullptr, nullptr, nullptr, nullptr);

    // out = O @ Wo + bo
    mma_gemm<0, 0><<<dim3(8, 32, 1), blk, GEMM_SMEM>>>(
        O, DM, 0, 0, Wo, DM, 0, 0, out, DM, 0, 0,
        NB * TT, DM, DM, bo, nullptr, nullptr, nullptr);
}

// round 3
// speedup vs baseline: 1.3925x; 1.0866x over previous
#include <cuda_runtime.h>
#include <cstdint>

#define TT 1024
#define DM 512
#define NB 4
#define NH 8
#define DK 64
#define LL 2047   // 2*T - 1
typedef long long ll;

// ---------------- scratch ----------------
__device__ float g_Q[NB * TT * DM];
__device__ float g_K[NB * TT * DM];
__device__ float g_V[NB * TT * DM];
__device__ float g_P[2048 * DM];
__device__ float g_R[32LL * 512 * LL];   // [b*8+h][m][l]
__device__ float g_O[NB * TT * DM];

// ---------------- helpers ----------------
__device__ __forceinline__ void split_tf32(float x, float& hi, float& lo) {
    uint32_t uh;
    asm("cvt.rna.tf32.f32 %0, %1;" : "=r"(uh) : "f"(x));
    hi = __uint_as_float(uh);
    float r = x - hi;
    uint32_t ul;
    asm("cvt.rna.tf32.f32 %0, %1;" : "=r"(ul) : "f"(r));
    lo = __uint_as_float(ul);
}

__device__ __forceinline__ void mma_tf32(float* d, const float* a, float b0, float b1) {
    asm volatile(
        "mma.sync.aligned.m16n8k8.row.col.f32.tf32.tf32.f32 "
        "{%0,%1,%2,%3}, {%4,%5,%6,%7}, {%8,%9}, {%0,%1,%2,%3};\n"
        : "+f"(d[0]), "+f"(d[1]), "+f"(d[2]), "+f"(d[3])
        : "r"(__float_as_uint(a[0])), "r"(__float_as_uint(a[1])),
          "r"(__float_as_uint(a[2])), "r"(__float_as_uint(a[3])),
          "r"(__float_as_uint(b0)), "r"(__float_as_uint(b1)));
}

__device__ __forceinline__ void cp_async16(uint32_t dst, const void* src, bool p) {
    asm volatile("cp.async.cg.shared.global [%0], [%1], 16, %2;\n"
                 :: "r"(dst), "l"(src), "r"(p ? 16 : 0));
}
__device__ __forceinline__ void cp_commit() { asm volatile("cp.async.commit_group;\n"); }
template <int N>
__device__ __forceinline__ void cp_wait() { asm volatile("cp.async.wait_group %0;\n" :: "n"(N)); }

// ---------------- pipelined tf32x3 GEMM ----------------
// C[M,N] = A[M,K] @ op(B) (+bias[n]) (+aBias[k] added to A rows if HASAB; K must be 64)
// 128x64 block tile, BK=32, 256 threads, cp.async 2-stage pipeline, raw f32 smem,
// tf32 split at fragment load.
#define ASTR 36
#define BSTR 72
#define TSTR 36
#define GEMM_SMEM ((2 * 128 * ASTR + 2 * 2304 + 64) * 4)

template <int TRANSB, int HASAB>
__global__ void __launch_bounds__(256) mma_gemm(
    const float* __restrict__ A, int lda, ll sAb, ll sAh,
    const float* __restrict__ B, int ldb, ll sBb, ll sBh,
    float* __restrict__ C, int ldc, ll sCb, ll sCh,
    int M, int N, int K,
    const float* __restrict__ bias, const float* __restrict__ aBias)
{
    extern __shared__ float sm[];
    float* As = sm;                       // [2][128][36]
    float* Bs = sm + 2 * 128 * ASTR;      // [2][2304] : NN [32][72], TN [64][36]
    float* ab_s = Bs + 2 * 2304;          // [64]

    const int z = blockIdx.z, b = z >> 3, h = z & 7;
    A += (ll)b * sAb + (ll)h * sAh;
    B += (ll)b * sBb + (ll)h * sBh;

    const int tid = threadIdx.x;
    const int lane = tid & 31, wid = tid >> 5;
    const int g = lane >> 2, t = lane & 3;
    const int wm = wid & 3, wn = wid >> 2;
    const int m0 = blockIdx.y * 128, n0 = blockIdx.x * 64;

    if (HASAB && tid < 64) ab_s[tid] = aBias[h * DK + tid];

    uint32_t sA = (uint32_t)__cvta_generic_to_shared(As);
    uint32_t sB = (uint32_t)__cvta_generic_to_shared(Bs);

    const int a_row = tid >> 3, a_c4 = (tid & 7) << 2;       // + 32*i rows
    const int bn_k = tid >> 4, bn_c4 = (tid & 15) << 2;      // NN
    const int bt_n = tid >> 3, bt_c4 = (tid & 7) << 2;       // TN

    auto stage = [&](int k0, int stg) {
        uint32_t aBase = sA + (uint32_t)(stg * 128 * ASTR) * 4;
        uint32_t bBase = sB + (uint32_t)(stg * 2304) * 4;
#pragma unroll
        for (int i = 0; i < 4; i++) {
            int row = a_row + 32 * i;
            cp_async16(aBase + (uint32_t)(row * ASTR + a_c4) * 4,
                       A + (ll)(m0 + row) * lda + k0 + a_c4, m0 + row < M);
        }
        if (!TRANSB) {
#pragma unroll
            for (int i = 0; i < 2; i++) {
                int k = bn_k + 16 * i;
                cp_async16(bBase + (uint32_t)(k * BSTR + bn_c4) * 4,
                           B + (ll)(k0 + k) * ldb + n0 + bn_c4, true);
            }
        } else {
#pragma unroll
            for (int i = 0; i < 2; i++) {
                int n = bt_n + 32 * i;
                cp_async16(bBase + (uint32_t)(n * TSTR + bt_c4) * 4,
                           B + (ll)(n0 + n) * ldb + k0 + bt_c4, n0 + n < N);
            }
        }
    };

    float d[2][4][4];
#pragma unroll
    for (int i = 0; i < 2; i++)
#pragma unroll
        for (int j = 0; j < 4; j++)
#pragma unroll
            for (int c = 0; c < 4; c++) d[i][j][c] = 0.f;

    const int nIter = K >> 5;
    stage(0, 0);
    cp_commit();

    for (int it = 0; it < nIter; it++) {
        __syncthreads();
        if (it + 1 < nIter) { stage((it + 1) << 5, (it + 1) & 1); cp_commit(); cp_wait<1>(); }
        else cp_wait<0>();
        __syncthreads();

        const float* pA = As + (it & 1) * 128 * ASTR;
        const float* pB = Bs + (it & 1) * 2304;
        const int k0 = it << 5;

#pragma unroll
        for (int ks = 0; ks < 4; ks++) {
            const int kb = ks * 8;
            float aH[2][4], aL[2][4];
            float ab0 = 0.f, ab1 = 0.f;
            if (HASAB) { ab0 = ab_s[k0 + kb + t]; ab1 = ab_s[k0 + kb + t + 4]; }
#pragma unroll
            for (int mt = 0; mt < 2; mt++) {
                int r0 = (wm * 32 + mt * 16 + g) * ASTR + kb;
                int r1 = r0 + 8 * ASTR;
                float v0 = pA[r0 + t] + ab0;
                float v1 = pA[r1 + t] + ab0;
                float v2 = pA[r0 + t + 4] + ab1;
                float v3 = pA[r1 + t + 4] + ab1;
                split_tf32(v0, aH[mt][0], aL[mt][0]);
                split_tf32(v1, aH[mt][1], aL[mt][1]);
                split_tf32(v2, aH[mt][2], aL[mt][2]);
                split_tf32(v3, aH[mt][3], aL[mt][3]);
            }
#pragma unroll
            for (int nt = 0; nt < 4; nt++) {
                int col = wn * 32 + nt * 8 + g;
                float r0, r1;
                if (!TRANSB) {
                    r0 = pB[(kb + t) * BSTR + col];
                    r1 = pB[(kb + t + 4) * BSTR + col];
                } else {
                    r0 = pB[col * TSTR + kb + t];
                    r1 = pB[col * TSTR + kb + t + 4];
                }
                float bh0, bl0, bh1, bl1;
                split_tf32(r0, bh0, bl0);
                split_tf32(r1, bh1, bl1);
#pragma unroll
                for (int mt = 0; mt < 2; mt++) {
                    mma_tf32(d[mt][nt], aH[mt], bh0, bh1);
                    mma_tf32(d[mt][nt], aH[mt], bl0, bl1);
                    mma_tf32(d[mt][nt], aL[mt], bh0, bh1);
                }
            }
        }
    }

    float* Cz = C + (ll)b * sCb + (ll)h * sCh;
#pragma unroll
    for (int mt = 0; mt < 2; mt++) {
        int row = m0 + wm * 32 + mt * 16 + g;
#pragma unroll
        for (int nt = 0; nt < 4; nt++) {
            int col = n0 + wn * 32 + nt * 8 + 2 * t;
            float b0 = (bias && col < N) ? bias[col] : 0.f;
            float b1 = (bias && col + 1 < N) ? bias[col + 1] : 0.f;
            if (row < M) {
                if (col < N)     Cz[(ll)row * ldc + col]     = d[mt][nt][0] + b0;
                if (col + 1 < N) Cz[(ll)row * ldc + col + 1] = d[mt][nt][1] + b1;
            }
            if (row + 8 < M) {
                if (col < N)     Cz[(ll)(row + 8) * ldc + col]     = d[mt][nt][2] + b0;
                if (col + 1 < N) Cz[(ll)(row + 8) * ldc + col + 1] = d[mt][nt][3] + b1;
            }
        }
    }
}

// ---------------- fused flash attention ----------------
// grid(16, 32): x = Q-block (64 t rows), y = (b,h). 128 threads (4 warps x 16 rows).
// scores = (Q+pbu)@K^T + relshift(R), *0.125, mask, online softmax, O += P@V.
#define KSTR 68
#define VSTR 76
#define FL_SMEM ((2 * 64 * KSTR + 2 * 64 * VSTR) * 4)

__global__ void __launch_bounds__(128) flash_attn(
    const float* __restrict__ Q, const float* __restrict__ Kg,
    const float* __restrict__ Vg, const float* __restrict__ pbu,
    const float* __restrict__ Rr, const unsigned char* __restrict__ maskp,
    float* __restrict__ Og)
{
    extern __shared__ float sm[];
    float* Ks = sm;                    // [2][64][68]
    float* Vs = sm + 2 * 64 * KSTR;    // [2][64][76]

    const int z = blockIdx.y, b = z >> 3, h = z & 7;
    const int t0 = blockIdx.x * 64;
    const int tid = threadIdx.x, lane = tid & 31, w = tid >> 5;
    const int g = lane >> 2, t = lane & 3;

    const float* Qb = Q + ((ll)(b * TT + t0)) * DM + h * DK;
    const float* Kb = Kg + ((ll)(b * TT)) * DM + h * DK;
    const float* Vb = Vg + ((ll)(b * TT)) * DM + h * DK;
    const ll rb = (ll)z * 512 * LL;
    const unsigned char* mb = maskp + (ll)b * TT * TT;

    // Q fragments in registers (+pbu), tf32-split
    float qh[8][4], ql[8][4];
    {
        int r0 = w * 16 + g, r1 = r0 + 8;
#pragma unroll
        for (int ks = 0; ks < 8; ks++) {
            int c0 = ks * 8 + t, c1 = c0 + 4;
            float u0 = pbu[h * DK + c0], u1 = pbu[h * DK + c1];
            split_tf32(Qb[(ll)r0 * DM + c0] + u0, qh[ks][0], ql[ks][0]);
            split_tf32(Qb[(ll)r1 * DM + c0] + u0, qh[ks][1], ql[ks][1]);
            split_tf32(Qb[(ll)r0 * DM + c1] + u1, qh[ks][2], ql[ks][2]);
            split_tf32(Qb[(ll)r1 * DM + c1] + u1, qh[ks][3], ql[ks][3]);
        }
    }

    float o[8][4];
#pragma unroll
    for (int i = 0; i < 8; i++)
#pragma unroll
        for (int j = 0; j < 4; j++) o[i][j] = 0.f;
    float mx0 = -1e30f, mx1 = -1e30f, l0 = 0.f, l1 = 0.f;

    uint32_t sK = (uint32_t)__cvta_generic_to_shared(Ks);
    uint32_t sV = (uint32_t)__cvta_generic_to_shared(Vs);

    auto loadKV = [&](int st, int buf) {
        const float* kp = Kb + (ll)(st * 64) * DM;
        const float* vp = Vb + (ll)(st * 64) * DM;
        uint32_t kBase = sK + (uint32_t)(buf * 64 * KSTR) * 4;
        uint32_t vBase = sV + (uint32_t)(buf * 64 * VSTR) * 4;
#pragma unroll
        for (int i = 0; i < 8; i++) {
            int idx = tid + 128 * i;
            int row = idx >> 4, c4 = (idx & 15) << 2;
            cp_async16(kBase + (uint32_t)(row * KSTR + c4) * 4, kp + (ll)row * DM + c4, true);
            cp_async16(vBase + (uint32_t)(row * VSTR + c4) * 4, vp + (ll)row * DM + c4, true);
        }
    };

    loadKV(0, 0);
    cp_commit();

    const int tg0 = t0 + w * 16 + g, tg1 = tg0 + 8;
    const float* R0 = Rr + rb + (ll)(tg0 >> 1) * LL;
    const float* R1 = Rr + rb + (ll)(tg1 >> 1) * LL;
    const int p0 = (tg0 & 1) << 10, p1 = (tg1 & 1) << 10;

    for (int st = 0; st < 16; st++) {
        __syncthreads();
        if (st + 1 < 16) { loadKV(st + 1, (st + 1) & 1); cp_commit(); cp_wait<1>(); }
        else cp_wait<0>();
        __syncthreads();

        const float* pKs = Ks + (st & 1) * 64 * KSTR;
        const float* pVs = Vs + (st & 1) * 64 * VSTR;

        // ---- scores = Q @ K^T (tf32x3) ----
        float sc[8][4];
#pragma unroll
        for (int i = 0; i < 8; i++)
#pragma unroll
            for (int j = 0; j < 4; j++) sc[i][j] = 0.f;
#pragma unroll
        for (int nt = 0; nt < 8; nt++) {
            int srow = (nt * 8 + g) * KSTR;
#pragma unroll
            for (int ks = 0; ks < 8; ks++) {
                float r0 = pKs[srow + ks * 8 + t];
                float r1 = pKs[srow + ks * 8 + t + 4];
                float bh0, bl0, bh1, bl1;
                split_tf32(r0, bh0, bl0);
                split_tf32(r1, bh1, bl1);
                mma_tf32(sc[nt], qh[ks], bh0, bh1);
                mma_tf32(sc[nt], qh[ks], bl0, bl1);
                mma_tf32(sc[nt], ql[ks], bh0, bh1);
            }
        }

        // ---- epilogue: pos + scale + mask, online softmax ----
        const int s0 = st * 64;
        float rmx0 = -1e30f, rmx1 = -1e30f;
#pragma unroll
        for (int nt = 0; nt < 8; nt++) {
            int s_ = s0 + nt * 8 + 2 * t;
            int la = s_ + p0, lb = s_ + p1;
            float pa0 = (la == LL) ? 0.f : R0[la];
            float pa1 = (la + 1 == LL) ? 0.f : R0[la + 1];
            float pb0 = (lb == LL) ? 0.f : R1[lb];
            float pb1 = (lb + 1 == LL) ? 0.f : R1[lb + 1];
            sc[nt][0] = mb[(ll)tg0 * TT + s_]     ? -1e9f : (sc[nt][0] + pa0) * 0.125f;
            sc[nt][1] = mb[(ll)tg0 * TT + s_ + 1] ? -1e9f : (sc[nt][1] + pa1) * 0.125f;
            sc[nt][2] = mb[(ll)tg1 * TT + s_]     ? -1e9f : (sc[nt][2] + pb0) * 0.125f;
            sc[nt][3] = mb[(ll)tg1 * TT + s_ + 1] ? -1e9f : (sc[nt][3] + pb1) * 0.125f;
            rmx0 = fmaxf(rmx0, fmaxf(sc[nt][0], sc[nt][1]));
            rmx1 = fmaxf(rmx1, fmaxf(sc[nt][2], sc[nt][3]));
        }
        rmx0 = fmaxf(rmx0, __shfl_xor_sync(0xffffffffu, rmx0, 1));
        rmx0 = fmaxf(rmx0, __shfl_xor_sync(0xffffffffu, rmx0, 2));
        rmx1 = fmaxf(rmx1, __shfl_xor_sync(0xffffffffu, rmx1, 1));
        rmx1 = fmaxf(rmx1, __shfl_xor_sync(0xffffffffu, rmx1, 2));

        float mn0 = fmaxf(mx0, rmx0), mn1 = fmaxf(mx1, rmx1);
        float al0 = __expf(mx0 - mn0), al1 = __expf(mx1 - mn1);
        float rs0 = 0.f, rs1 = 0.f;
#pragma unroll
        for (int nt = 0; nt < 8; nt++) {
            sc[nt][0] = __expf(sc[nt][0] - mn0);
            sc[nt][1] = __expf(sc[nt][1] - mn0);
            sc[nt][2] = __expf(sc[nt][2] - mn1);
            sc[nt][3] = __expf(sc[nt][3] - mn1);
            rs0 += sc[nt][0] + sc[nt][1];
            rs1 += sc[nt][2] + sc[nt][3];
        }
        rs0 += __shfl_xor_sync(0xffffffffu, rs0, 1);
        rs0 += __shfl_xor_sync(0xffffffffu, rs0, 2);
        rs1 += __shfl_xor_sync(0xffffffffu, rs1, 1);
        rs1 += __shfl_xor_sync(0xffffffffu, rs1, 2);
        l0 = l0 * al0 + rs0;
        l1 = l1 * al1 + rs1;
        mx0 = mn0; mx1 = mn1;
#pragma unroll
        for (int dt = 0; dt < 8; dt++) {
            o[dt][0] *= al0; o[dt][1] *= al0;
            o[dt][2] *= al1; o[dt][3] *= al1;
        }

        // ---- O += P @ V  (accumulator fragments reused as A via positional-k perm) ----
#pragma unroll
        for (int s8 = 0; s8 < 8; s8++) {
            float araw[4] = { sc[s8][0], sc[s8][2], sc[s8][1], sc[s8][3] };
            float ah[4], al_[4];
            split_tf32(araw[0], ah[0], al_[0]);
            split_tf32(araw[1], ah[1], al_[1]);
            split_tf32(araw[2], ah[2], al_[2]);
            split_tf32(araw[3], ah[3], al_[3]);
            int vr0 = (s8 * 8 + 2 * t) * VSTR, vr1 = vr0 + VSTR;
#pragma unroll
            for (int dt = 0; dt < 8; dt++) {
                int col = dt * 8 + g;
                float r0 = pVs[vr0 + col], r1 = pVs[vr1 + col];
                float bh0, bl0, bh1, bl1;
                split_tf32(r0, bh0, bl0);
                split_tf32(r1, bh1, bl1);
                mma_tf32(o[dt], ah, bh0, bh1);
                mma_tf32(o[dt], ah, bl0, bl1);
                mma_tf32(o[dt], al_, bh0, bh1);
            }
        }
    }

    float inv0 = 1.f / l0, inv1 = 1.f / l1;
    float* o0 = Og + ((ll)(b * TT + tg0)) * DM + h * DK;
    float* o1 = Og + ((ll)(b * TT + tg1)) * DM + h * DK;
#pragma unroll
    for (int dt = 0; dt < 8; dt++) {
        int d0 = dt * 8 + 2 * t;
        o0[d0] = o[dt][0] * inv0; o0[d0 + 1] = o[dt][1] * inv0;
        o1[d0] = o[dt][2] * inv1; o1[d0 + 1] = o[dt][3] * inv1;
    }
}

// ---------------- launch ----------------
extern "C" void kernel_launch(void* const* d_in, const int* in_sizes, int n_in,
                              void* d_out, int out_size)
{
    const float* x   = (const float*)d_in[0];
    const float* pos = (const float*)d_in[1];
    const unsigned char* mask = (const unsigned char*)d_in[2];
    const float* Wq = (const float*)d_in[3];  const float* bq = (const float*)d_in[4];
    const float* Wk = (const float*)d_in[5];  const float* bk = (const float*)d_in[6];
    const float* Wv = (const float*)d_in[7];  const float* bv = (const float*)d_in[8];
    const float* Wp = (const float*)d_in[9];  const float* bp = (const float*)d_in[10];
    const float* Wo = (const float*)d_in[11]; const float* bo = (const float*)d_in[12];
    const float* pbu = (const float*)d_in[13];
    const float* pbv = (const float*)d_in[14];
    float* out = (float*)d_out;

    float *Q, *K, *V, *P, *R, *O;
    cudaGetSymbolAddress((void**)&Q, g_Q);
    cudaGetSymbolAddress((void**)&K, g_K);
    cudaGetSymbolAddress((void**)&V, g_V);
    cudaGetSymbolAddress((void**)&P, g_P);
    cudaGetSymbolAddress((void**)&R, g_R);
    cudaGetSymbolAddress((void**)&O, g_O);

    cudaFuncSetAttribute(mma_gemm<0, 0>, cudaFuncAttributeMaxDynamicSharedMemorySize, GEMM_SMEM);
    cudaFuncSetAttribute(mma_gemm<1, 1>, cudaFuncAttributeMaxDynamicSharedMemorySize, GEMM_SMEM);
    cudaFuncSetAttribute(flash_attn, cudaFuncAttributeMaxDynamicSharedMemorySize, FL_SMEM);

    dim3 blk(256);

    mma_gemm<0, 0><<<dim3(8, 32, 1), blk, GEMM_SMEM>>>(
        x, DM, 0, 0, Wq, DM, 0, 0, Q, DM, 0, 0, NB * TT, DM, DM, bq, nullptr);
    mma_gemm<0, 0><<<dim3(8, 32, 1), blk, GEMM_SMEM>>>(
        x, DM, 0, 0, Wk, DM, 0, 0, K, DM, 0, 0, NB * TT, DM, DM, bk, nullptr);
    mma_gemm<0, 0><<<dim3(8, 32, 1), blk, GEMM_SMEM>>>(
        x, DM, 0, 0, Wv, DM, 0, 0, V, DM, 0, 0, NB * TT, DM, DM, bv, nullptr);
    mma_gemm<0, 0><<<dim3(8, 16, 1), blk, GEMM_SMEM>>>(
        pos, DM, 0, 0, Wp, DM, 0, 0, P, DM, 0, 0, LL, DM, DM, bp, nullptr);

    // R = (Q[512:] + pos_bias_v) @ P^T per (b,h): M=512, N=2047, K=64
    mma_gemm<1, 1><<<dim3(32, 4, 32), blk, GEMM_SMEM>>>(
        Q + 512 * DM, DM, (ll)TT * DM, DK,
        P, DM, 0, DK,
        R, LL, 8LL * 512 * LL, (ll)512 * LL,
        512, LL, DK, nullptr, pbv);

    // fused scores + softmax + AV
    flash_attn<<<dim3(16, 32), dim3(128), FL_SMEM>>>(Q, K, V, pbu, R, mask, O);

    // out = O @ Wo + bo
    mma_gemm<0, 0><<<dim3(8, 32, 1), blk, GEMM_SMEM>>>(
        O, DM, 0, 0, Wo, DM, 0, 0, out, DM, 0, 0,
        NB * TT, DM, DM, bo, nullptr);
}